// round 1
// baseline (speedup 1.0000x reference)
#include <cuda_runtime.h>

// GlobalFilter: out = irfft2( rfft2(x, ortho) * W, ortho ), per (batch, channel)
// x: [512, 196, 384] f32 ; W: [14, 8, 384, 2] f32 ; out: [512, 196, 384] f32
//
// Decomposition (all 14-point DFTs, twiddles are compile-time immediates):
//   Stage A: per (n1, c): rfft-14 over n2 (real->8 complex), x read straight
//            from global (lane = channel -> 128B coalesced lines), F -> smem.
//   Stage B: per (k2, c): forward complex DFT-14 over n1, multiply by
//            W[k1][k2][c]/196, inverse complex DFT-14 over k1 — all in
//            registers of one thread (column ownership), write back to smem.
//   Stage C: per (n1, c): c2r over k2 (imag of bins 0 and 7 drop out),
//            write straight to global.

#define NBATCH 512
#define GRID_A 14
#define HALF_W 8
#define NCH    384
#define CT_TILE 32
#define NTHREADS 256

// acc += val * coef, with coef a compile-time constant: folds 0 / +-1 cases.
#define MAC(acc, val, coef)                              \
    do {                                                 \
        const float _cf = (coef);                        \
        if (_cf == 1.0f)        (acc) += (val);          \
        else if (_cf == -1.0f)  (acc) -= (val);          \
        else if (_cf != 0.0f)   (acc) = fmaf((val), _cf, (acc)); \
    } while (0)

__global__ __launch_bounds__(NTHREADS)
void gf_kernel(const float* __restrict__ x,
               const float* __restrict__ cw,
               float* __restrict__ out)
{
    // twiddle tables: ct[j]=cos(2*pi*j/14), st[j]=sin(2*pi*j/14)
    const float ct[14] = {
         1.0f,                  0.9009688679024191f,  0.6234898018587336f,
         0.2225209339563144f,  -0.2225209339563144f, -0.6234898018587336f,
        -0.9009688679024191f,  -1.0f,                -0.9009688679024191f,
        -0.6234898018587336f,  -0.2225209339563144f,  0.2225209339563144f,
         0.6234898018587336f,   0.9009688679024191f };
    const float st[14] = {
         0.0f,                  0.4338837391175581f,  0.7818314824680298f,
         0.9749279121818236f,   0.9749279121818236f,  0.7818314824680298f,
         0.4338837391175581f,   0.0f,                -0.4338837391175581f,
        -0.7818314824680298f,  -0.9749279121818236f, -0.9749279121818236f,
        -0.7818314824680298f,  -0.4338837391175581f };

    __shared__ float2 Fs[GRID_A][HALF_W][CT_TILE];

    const int b  = blockIdx.x;
    const int c0 = blockIdx.y * CT_TILE;
    const int tid = threadIdx.x;

    // ---------------- Stage A: row rfft (contract n2) ----------------
    for (int t = tid; t < GRID_A * CT_TILE; t += NTHREADS) {
        const int c  = t & (CT_TILE - 1);
        const int n1 = t >> 5;
        const float* xrow = x + ((size_t)(b * 196 + n1 * 14)) * NCH + c0 + c;
        float in[14];
#pragma unroll
        for (int n = 0; n < 14; n++) in[n] = xrow[n * NCH];
#pragma unroll
        for (int k = 0; k < HALF_W; k++) {
            float fr = 0.0f, fi = 0.0f;
#pragma unroll
            for (int n = 0; n < 14; n++) {
                const int j = (k * n) % 14;
                MAC(fr, in[n],  ct[j]);
                MAC(fi, in[n], -st[j]);
            }
            Fs[n1][k][c] = make_float2(fr, fi);
        }
    }
    __syncthreads();

    // ------- Stage B: fwd DFT over n1, weight mul, inv DFT over k1 -------
    {
        const int c  = tid & (CT_TILE - 1);
        const int k2 = tid >> 5;   // 0..7, all 256 threads active
        float2 v[14];
#pragma unroll
        for (int n = 0; n < 14; n++) v[n] = Fs[n][k2][c];

        float2 g[14];
#pragma unroll
        for (int k = 0; k < 14; k++) {
            float gr = 0.0f, gi = 0.0f;
#pragma unroll
            for (int n = 0; n < 14; n++) {
                const int j = (k * n) % 14;
                // (vr + i vi) * (c - i s)
                MAC(gr, v[n].x,  ct[j]);
                MAC(gr, v[n].y,  st[j]);
                MAC(gi, v[n].y,  ct[j]);
                MAC(gi, v[n].x, -st[j]);
            }
            // multiply by W[k][k2][c0+c] / 196 (ortho norm folded here)
            const float* wp = cw + (((size_t)k * HALF_W + k2) * NCH + c0 + c) * 2;
            const float wr = wp[0] * (1.0f / 196.0f);
            const float wi = wp[1] * (1.0f / 196.0f);
            g[k] = make_float2(fmaf(gr, wr, -gi * wi), fmaf(gr, wi, gi * wr));
        }
#pragma unroll
        for (int n = 0; n < 14; n++) {
            float ur = 0.0f, ui = 0.0f;
#pragma unroll
            for (int k = 0; k < 14; k++) {
                const int j = (k * n) % 14;
                // (gr + i gi) * (c + i s)
                MAC(ur, g[k].x,  ct[j]);
                MAC(ur, g[k].y, -st[j]);
                MAC(ui, g[k].y,  ct[j]);
                MAC(ui, g[k].x,  st[j]);
            }
            Fs[n][k2][c] = make_float2(ur, ui);
        }
    }
    __syncthreads();

    // ---------------- Stage C: c2r over k2, write out ----------------
    for (int t = tid; t < GRID_A * CT_TILE; t += NTHREADS) {
        const int c  = t & (CT_TILE - 1);
        const int n1 = t >> 5;
        float2 v[HALF_W];
#pragma unroll
        for (int k = 0; k < HALF_W; k++) v[k] = Fs[n1][k][c];
        float* orow = out + ((size_t)(b * 196 + n1 * 14)) * NCH + c0 + c;
#pragma unroll
        for (int n = 0; n < 14; n++) {
            // bins 0 and 7: imaginary parts ignored (c2r semantics)
            float o = v[0].x;
            if (n & 1) o -= v[7].x; else o += v[7].x;
#pragma unroll
            for (int k = 1; k < 7; k++) {
                const int j = (k * n) % 14;
                MAC(o, v[k].x,  2.0f * ct[j]);
                MAC(o, v[k].y, -2.0f * st[j]);
            }
            orow[n * NCH] = o;
        }
    }
}

extern "C" void kernel_launch(void* const* d_in, const int* in_sizes, int n_in,
                              void* d_out, int out_size)
{
    const float* x  = (const float*)d_in[0];
    const float* cw = (const float*)d_in[1];
    float* out = (float*)d_out;
    (void)in_sizes; (void)n_in; (void)out_size;

    dim3 grid(NBATCH, NCH / CT_TILE);
    gf_kernel<<<grid, NTHREADS>>>(x, cw, out);
}

// round 2
// speedup vs baseline: 1.2474x; 1.2474x over previous
#include <cuda_runtime.h>

// GlobalFilter: out = irfft2( rfft2(x, ortho) * W, ortho ) per (batch, channel)
// x: [512, 196, 384] f32 ; W: [14, 8, 384, 2] f32 ; out: [512, 196, 384] f32
//
// All DFT-14s factored as Cooley-Tukey 2x7 with conjugate-pair folding inside
// the DFT-7 (3x fewer fma than the naive O(N^2) version of round 1).
//   Stage A: rfft-14 over n2 (real->8 bins) straight from global, F -> smem
//   Stage B: fwd cDFT-14 over n1, weight mul, inv cDFT-14 over k1, registers
//   Stage C: c2r-14 over k2 (fold k/k+7 -> two conj-symmetric IDFT-7s),
//            1/196 ortho norm folded into compile-time constants, write global

#define NBATCH 512
#define HALF_W 8
#define NCH    384
#define CT_TILE 32
#define NTHREADS 256

#define C7_TAB {1.0f, 0.6234898018587336f, -0.2225209339563144f, -0.9009688679024191f, \
                -0.9009688679024191f, -0.2225209339563144f, 0.6234898018587336f}
#define S7_TAB {0.0f, 0.7818314824680298f, 0.9749279121818236f, 0.4338837391175581f, \
                -0.4338837391175581f, -0.9749279121818236f, -0.7818314824680298f}
#define CT14_TAB {1.0f, 0.9009688679024191f, 0.6234898018587336f, 0.2225209339563144f, \
                  -0.2225209339563144f, -0.6234898018587336f, -0.9009688679024191f}
#define ST14_TAB {0.0f, 0.4338837391175581f, 0.7818314824680298f, 0.9749279121818236f, \
                  0.9749279121818236f, 0.7818314824680298f, 0.4338837391175581f}

__device__ __forceinline__ float2 mk(float a, float b) { return make_float2(a, b); }

// Symmetric complex DFT-7. SGN=-1: X[k]=sum v[n] e^{-2pi i kn/7}; SGN=+1: e^{+}.
template<int SGN>
__device__ __forceinline__ void cdft7(const float2 v[7], float2 X[7]) {
    const float c7[7] = C7_TAB;
    const float s7[7] = S7_TAB;
    float2 tp[4], tm[4];
#pragma unroll
    for (int n = 1; n <= 3; n++) {
        tp[n] = mk(v[n].x + v[7 - n].x, v[n].y + v[7 - n].y);
        tm[n] = mk(v[n].x - v[7 - n].x, v[n].y - v[7 - n].y);
    }
    X[0] = mk(v[0].x + tp[1].x + tp[2].x + tp[3].x,
              v[0].y + tp[1].y + tp[2].y + tp[3].y);
#pragma unroll
    for (int k = 1; k <= 3; k++) {
        float Ar = v[0].x, Ai = v[0].y, Br = 0.0f, Bi = 0.0f;
#pragma unroll
        for (int n = 1; n <= 3; n++) {
            const int j = (k * n) % 7;
            Ar = fmaf(tp[n].x, c7[j], Ar);
            Ai = fmaf(tp[n].y, c7[j], Ai);
            Br = fmaf(tm[n].x, s7[j], Br);
            Bi = fmaf(tm[n].y, s7[j], Bi);
        }
        if (SGN < 0) { X[k] = mk(Ar + Bi, Ai - Br); X[7 - k] = mk(Ar - Bi, Ai + Br); }
        else         { X[k] = mk(Ar - Bi, Ai + Br); X[7 - k] = mk(Ar + Bi, Ai - Br); }
    }
}

// Complex DFT-14 via DIT 2x7. SGN=-1 fwd, SGN=+1 inv.
template<int SGN>
__device__ __forceinline__ void cdft14(const float2 v[14], float2 X[14]) {
    const float ct[7] = CT14_TAB;
    const float st[7] = ST14_TAB;
    float2 ve[7], vo[7], E[7], O[7];
#pragma unroll
    for (int n = 0; n < 7; n++) { ve[n] = v[2 * n]; vo[n] = v[2 * n + 1]; }
    cdft7<SGN>(ve, E);
    cdft7<SGN>(vo, O);
    X[0] = mk(E[0].x + O[0].x, E[0].y + O[0].y);
    X[7] = mk(E[0].x - O[0].x, E[0].y - O[0].y);
#pragma unroll
    for (int k = 1; k < 7; k++) {
        float tr, ti;
        if (SGN < 0) {  // (c - i s)(or + i oi)
            tr = fmaf(ct[k], O[k].x,  st[k] * O[k].y);
            ti = fmaf(ct[k], O[k].y, -st[k] * O[k].x);
        } else {        // (c + i s)(or + i oi)
            tr = fmaf(ct[k], O[k].x, -st[k] * O[k].y);
            ti = fmaf(ct[k], O[k].y,  st[k] * O[k].x);
        }
        X[k]     = mk(E[k].x + tr, E[k].y + ti);
        X[k + 7] = mk(E[k].x - tr, E[k].y - ti);
    }
}

// Real forward DFT-7: bins 0..3 (0 purely real).
__device__ __forceinline__ void rdft7(const float r[7], float& R0, float2 R[4]) {
    const float c7[7] = C7_TAB;
    const float s7[7] = S7_TAB;
    float tp[4], tm[4];
#pragma unroll
    for (int n = 1; n <= 3; n++) { tp[n] = r[n] + r[7 - n]; tm[n] = r[n] - r[7 - n]; }
    R0 = r[0] + tp[1] + tp[2] + tp[3];
#pragma unroll
    for (int k = 1; k <= 3; k++) {
        float re = r[0], im = 0.0f;
#pragma unroll
        for (int n = 1; n <= 3; n++) {
            const int j = (k * n) % 7;
            re = fmaf(tp[n],  c7[j], re);
            im = fmaf(tm[n], -s7[j], im);
        }
        R[k] = mk(re, im);
    }
}

__global__ __launch_bounds__(NTHREADS, 3)
void gf_kernel(const float* __restrict__ x,
               const float* __restrict__ cw,
               float* __restrict__ out)
{
    __shared__ float2 Fs[14][HALF_W][CT_TILE];

    const int b   = blockIdx.x;
    const int c0  = blockIdx.y * CT_TILE;
    const int tid = threadIdx.x;

    // ---------------- Stage A: row rfft-14 over n2 ----------------
    {
        const float ct[7] = CT14_TAB;
        const float st[7] = ST14_TAB;
        for (int t = tid; t < 14 * CT_TILE; t += NTHREADS) {
            const int c  = t & (CT_TILE - 1);
            const int n1 = t >> 5;
            const float* xrow = x + ((size_t)(b * 196 + n1 * 14)) * NCH + c0 + c;
            float in[14];
#pragma unroll
            for (int n = 0; n < 14; n++) in[n] = xrow[n * NCH];

            float ev[7], od[7];
#pragma unroll
            for (int n = 0; n < 7; n++) { ev[n] = in[2 * n]; od[n] = in[2 * n + 1]; }
            float E0, O0;
            float2 E[4], O[4];
            rdft7(ev, E0, E);
            rdft7(od, O0, O);

            Fs[n1][0][c] = mk(E0 + O0, 0.0f);
            Fs[n1][7][c] = mk(E0 - O0, 0.0f);
#pragma unroll
            for (int k = 1; k <= 3; k++) {  // F[k] = E[k] + (c - i s) O[k]
                const float tr = fmaf(ct[k], O[k].x,  st[k] * O[k].y);
                const float ti = fmaf(ct[k], O[k].y, -st[k] * O[k].x);
                Fs[n1][k][c] = mk(E[k].x + tr, E[k].y + ti);
            }
#pragma unroll
            for (int k = 4; k <= 6; k++) {  // E'[k]=conj(E[7-k]), O'[k]=conj(O[7-k])
                const float orr = O[7 - k].x, oi = O[7 - k].y;
                const float tr =  fmaf(ct[k], orr, -st[k] * oi);
                const float ti = -fmaf(ct[k], oi,   st[k] * orr);
                Fs[n1][k][c] = mk(E[7 - k].x + tr, -E[7 - k].y + ti);
            }
        }
    }
    __syncthreads();

    // ------ Stage B: fwd cDFT-14 over n1, weight mul, inv cDFT-14 ------
    {
        const int c  = tid & (CT_TILE - 1);
        const int k2 = tid >> 5;  // 0..7
        float2 v[14];
#pragma unroll
        for (int n = 0; n < 14; n++) v[n] = Fs[n][k2][c];

        float2 G[14];
        cdft14<-1>(v, G);

        float2 g[14];
#pragma unroll
        for (int k = 0; k < 14; k++) {
            const float* wp = cw + (((size_t)k * HALF_W + k2) * NCH + c0 + c) * 2;
            const float wr = wp[0];
            const float wi = wp[1];
            g[k] = mk(fmaf(G[k].x, wr, -G[k].y * wi),
                      fmaf(G[k].x, wi,  G[k].y * wr));
        }

        float2 U[14];
        cdft14<1>(g, U);
#pragma unroll
        for (int n = 0; n < 14; n++) Fs[n][k2][c] = U[n];
    }
    __syncthreads();

    // ---------------- Stage C: c2r-14 over k2 ----------------
    {
        const float c7[7] = C7_TAB;
        const float s7[7] = S7_TAB;
        const float ct[7] = CT14_TAB;
        const float st[7] = ST14_TAB;
        for (int t = tid; t < 14 * CT_TILE; t += NTHREADS) {
            const int c  = t & (CT_TILE - 1);
            const int n1 = t >> 5;
            float2 V[HALF_W];
#pragma unroll
            for (int k = 0; k < HALF_W; k++) V[k] = Fs[n1][k][c];

            // fold k / k+7: a_k = V[k] + conj(V[7-k]) (conj-symmetric),
            //               b_k = (V[k] - conj(V[7-k])) * e^{+2pi i k/14}
            const float a0s = (V[0].x + V[7].x) * (1.0f / 196.0f);
            const float b0s = (V[0].x - V[7].x) * (1.0f / 196.0f);
            float2 a[4], bb[4];
#pragma unroll
            for (int k = 1; k <= 3; k++) {
                a[k] = mk(V[k].x + V[7 - k].x, V[k].y - V[7 - k].y);
                const float dr = V[k].x - V[7 - k].x;
                const float di = V[k].y + V[7 - k].y;
                bb[k] = mk(fmaf(ct[k], dr, -st[k] * di),
                           fmaf(ct[k], di,  st[k] * dr));
            }

            float* orow = out + ((size_t)(b * 196 + n1 * 14)) * NCH + c0 + c;
#pragma unroll
            for (int m = 0; m < 7; m++) {
                float evn = a0s, odd = b0s;
#pragma unroll
                for (int k = 1; k <= 3; k++) {
                    const int j = (k * m) % 7;
                    // out = sum 2*Re(z e^{+i th}) / 196 ; constants fold at compile time
                    evn = fmaf(a[k].x,   c7[j] * (2.0f / 196.0f), evn);
                    evn = fmaf(a[k].y,  -s7[j] * (2.0f / 196.0f), evn);
                    odd = fmaf(bb[k].x,  c7[j] * (2.0f / 196.0f), odd);
                    odd = fmaf(bb[k].y, -s7[j] * (2.0f / 196.0f), odd);
                }
                orow[(2 * m)     * NCH] = evn;
                orow[(2 * m + 1) * NCH] = odd;
            }
        }
    }
}

extern "C" void kernel_launch(void* const* d_in, const int* in_sizes, int n_in,
                              void* d_out, int out_size)
{
    const float* x  = (const float*)d_in[0];
    const float* cw = (const float*)d_in[1];
    float* out = (float*)d_out;
    (void)in_sizes; (void)n_in; (void)out_size;

    dim3 grid(NBATCH, NCH / CT_TILE);
    gf_kernel<<<grid, NTHREADS>>>(x, cw, out);
}

// round 3
// speedup vs baseline: 1.5092x; 1.2098x over previous
#include <cuda_runtime.h>

// GlobalFilter: out = irfft2( rfft2(x, ortho) * W, ortho ) per (batch, channel)
// x: [512, 196, 384] f32 ; W: [14, 8, 384, 2] f32 ; out: [512, 196, 384] f32
//
// Round 3: Stage B restructured as fwd-DIT + fused weight-mul + inv-DIF over
// the k/k+7 pairs, all in-place in E[7]/O[7] (halves register pressure), and
// 128-thread CTAs (CT_TILE=16) for 8 CTAs/SM phase overlap.

#define NBATCH 512
#define HALF_W 8
#define NCH    384
#define CT_TILE 16
#define NTHREADS 128

#define C7_TAB {1.0f, 0.6234898018587336f, -0.2225209339563144f, -0.9009688679024191f, \
                -0.9009688679024191f, -0.2225209339563144f, 0.6234898018587336f}
#define S7_TAB {0.0f, 0.7818314824680298f, 0.9749279121818236f, 0.4338837391175581f, \
                -0.4338837391175581f, -0.9749279121818236f, -0.7818314824680298f}
#define CT14_TAB {1.0f, 0.9009688679024191f, 0.6234898018587336f, 0.2225209339563144f, \
                  -0.2225209339563144f, -0.6234898018587336f, -0.9009688679024191f}
#define ST14_TAB {0.0f, 0.4338837391175581f, 0.7818314824680298f, 0.9749279121818236f, \
                  0.9749279121818236f, 0.7818314824680298f, 0.4338837391175581f}

__device__ __forceinline__ float2 mk(float a, float b) { return make_float2(a, b); }

// Symmetric complex DFT-7 into registers. SGN=-1: e^{-2pi i kn/7}; +1: e^{+}.
template<int SGN>
__device__ __forceinline__ void cdft7(const float2 v[7], float2 X[7]) {
    const float c7[7] = C7_TAB;
    const float s7[7] = S7_TAB;
    float2 tp[4], tm[4];
#pragma unroll
    for (int n = 1; n <= 3; n++) {
        tp[n] = mk(v[n].x + v[7 - n].x, v[n].y + v[7 - n].y);
        tm[n] = mk(v[n].x - v[7 - n].x, v[n].y - v[7 - n].y);
    }
    X[0] = mk(v[0].x + tp[1].x + tp[2].x + tp[3].x,
              v[0].y + tp[1].y + tp[2].y + tp[3].y);
#pragma unroll
    for (int k = 1; k <= 3; k++) {
        float Ar = v[0].x, Ai = v[0].y, Br = 0.0f, Bi = 0.0f;
#pragma unroll
        for (int n = 1; n <= 3; n++) {
            const int j = (k * n) % 7;
            Ar = fmaf(tp[n].x, c7[j], Ar);
            Ai = fmaf(tp[n].y, c7[j], Ai);
            Br = fmaf(tm[n].x, s7[j], Br);
            Bi = fmaf(tm[n].y, s7[j], Bi);
        }
        if (SGN < 0) { X[k] = mk(Ar + Bi, Ai - Br); X[7 - k] = mk(Ar - Bi, Ai + Br); }
        else         { X[k] = mk(Ar - Bi, Ai + Br); X[7 - k] = mk(Ar + Bi, Ai - Br); }
    }
}

// Same DFT-7 but stores results straight to (strided) shared memory — keeps
// the 14 output complexes out of the register file.
template<int SGN>
__device__ __forceinline__ void cdft7_store(const float2 v[7], float2* base, const int strideF2) {
    const float c7[7] = C7_TAB;
    const float s7[7] = S7_TAB;
    float2 tp[4], tm[4];
#pragma unroll
    for (int n = 1; n <= 3; n++) {
        tp[n] = mk(v[n].x + v[7 - n].x, v[n].y + v[7 - n].y);
        tm[n] = mk(v[n].x - v[7 - n].x, v[n].y - v[7 - n].y);
    }
    base[0] = mk(v[0].x + tp[1].x + tp[2].x + tp[3].x,
                 v[0].y + tp[1].y + tp[2].y + tp[3].y);
#pragma unroll
    for (int k = 1; k <= 3; k++) {
        float Ar = v[0].x, Ai = v[0].y, Br = 0.0f, Bi = 0.0f;
#pragma unroll
        for (int n = 1; n <= 3; n++) {
            const int j = (k * n) % 7;
            Ar = fmaf(tp[n].x, c7[j], Ar);
            Ai = fmaf(tp[n].y, c7[j], Ai);
            Br = fmaf(tm[n].x, s7[j], Br);
            Bi = fmaf(tm[n].y, s7[j], Bi);
        }
        if (SGN < 0) {
            base[k * strideF2]       = mk(Ar + Bi, Ai - Br);
            base[(7 - k) * strideF2] = mk(Ar - Bi, Ai + Br);
        } else {
            base[k * strideF2]       = mk(Ar - Bi, Ai + Br);
            base[(7 - k) * strideF2] = mk(Ar + Bi, Ai - Br);
        }
    }
}

// Real forward DFT-7: bins 0..3 (bin 0 purely real).
__device__ __forceinline__ void rdft7(const float r[7], float& R0, float2 R[4]) {
    const float c7[7] = C7_TAB;
    const float s7[7] = S7_TAB;
    float tp[4], tm[4];
#pragma unroll
    for (int n = 1; n <= 3; n++) { tp[n] = r[n] + r[7 - n]; tm[n] = r[n] - r[7 - n]; }
    R0 = r[0] + tp[1] + tp[2] + tp[3];
#pragma unroll
    for (int k = 1; k <= 3; k++) {
        float re = r[0], im = 0.0f;
#pragma unroll
        for (int n = 1; n <= 3; n++) {
            const int j = (k * n) % 7;
            re = fmaf(tp[n],  c7[j], re);
            im = fmaf(tm[n], -s7[j], im);
        }
        R[k] = mk(re, im);
    }
}

__global__ __launch_bounds__(NTHREADS, 8)
void gf_kernel(const float* __restrict__ x,
               const float* __restrict__ cw,
               float* __restrict__ out)
{
    __shared__ float2 Fs[14][HALF_W][CT_TILE];   // 14.3 KB

    const int b   = blockIdx.x;
    const int c0  = blockIdx.y * CT_TILE;
    const int tid = threadIdx.x;

    // ---------------- Stage A: row rfft-14 over n2 ----------------
    {
        const float ct[7] = CT14_TAB;
        const float st[7] = ST14_TAB;
        for (int t = tid; t < 14 * CT_TILE; t += NTHREADS) {
            const int c  = t & (CT_TILE - 1);
            const int n1 = t / CT_TILE;
            const float* xrow = x + ((size_t)(b * 196 + n1 * 14)) * NCH + c0 + c;
            float in[14];
#pragma unroll
            for (int n = 0; n < 14; n++) in[n] = xrow[n * NCH];

            float ev[7], od[7];
#pragma unroll
            for (int n = 0; n < 7; n++) { ev[n] = in[2 * n]; od[n] = in[2 * n + 1]; }
            float E0, O0;
            float2 E[4], O[4];
            rdft7(ev, E0, E);
            rdft7(od, O0, O);

            Fs[n1][0][c] = mk(E0 + O0, 0.0f);
            Fs[n1][7][c] = mk(E0 - O0, 0.0f);
#pragma unroll
            for (int k = 1; k <= 3; k++) {  // F[k] = E[k] + (c - i s) O[k]
                const float tr = fmaf(ct[k], O[k].x,  st[k] * O[k].y);
                const float ti = fmaf(ct[k], O[k].y, -st[k] * O[k].x);
                Fs[n1][k][c] = mk(E[k].x + tr, E[k].y + ti);
            }
#pragma unroll
            for (int k = 4; k <= 6; k++) {  // E'[k]=conj(E[7-k]), O'[k]=conj(O[7-k])
                const float orr = O[7 - k].x, oi = O[7 - k].y;
                const float tr =  fmaf(ct[k], orr, -st[k] * oi);
                const float ti = -fmaf(ct[k], oi,   st[k] * orr);
                Fs[n1][k][c] = mk(E[7 - k].x + tr, -E[7 - k].y + ti);
            }
        }
    }
    __syncthreads();

    // ---- Stage B: fwd DIT-14 + weight mul + inv DIF-14, in-place pairs ----
    {
        const float ct[7] = CT14_TAB;
        const float st[7] = ST14_TAB;
        const int c  = tid & (CT_TILE - 1);
        const int k2 = tid / CT_TILE;   // 0..7

        float2 E[7], O[7];
        {
            float2 ve[7];
#pragma unroll
            for (int n = 0; n < 7; n++) ve[n] = Fs[2 * n][k2][c];
            cdft7<-1>(ve, E);
#pragma unroll
            for (int n = 0; n < 7; n++) ve[n] = Fs[2 * n + 1][k2][c];
            cdft7<-1>(ve, O);
        }

        // weights as float2; index (k1*8 + k2)*384 + ch
        const float2* W = (const float2*)cw + ((size_t)k2 * NCH + c0 + c);
#pragma unroll
        for (int k = 0; k < 7; k++) {
            float Tr, Ti;
            if (k == 0) { Tr = O[0].x; Ti = O[0].y; }
            else {
                Tr = fmaf(ct[k], O[k].x,  st[k] * O[k].y);
                Ti = fmaf(ct[k], O[k].y, -st[k] * O[k].x);
            }
            const float Gr = E[k].x + Tr, Gi = E[k].y + Ti;   // G[k]
            const float Hr = E[k].x - Tr, Hi = E[k].y - Ti;   // G[k+7]
            const float2 wa = W[(size_t)k * (HALF_W * NCH)];
            const float2 wb = W[(size_t)(k + 7) * (HALF_W * NCH)];
            const float gr = fmaf(Gr, wa.x, -Gi * wa.y);
            const float gi = fmaf(Gr, wa.y,  Gi * wa.x);
            const float hr = fmaf(Hr, wb.x, -Hi * wb.y);
            const float hi = fmaf(Hr, wb.y,  Hi * wb.x);
            // DIF fold: p = g+h (even outputs), q = (g-h) e^{+2pi i k/14} (odd)
            E[k] = mk(gr + hr, gi + hi);
            const float dr = gr - hr, di = gi - hi;
            if (k == 0) O[0] = mk(dr, di);
            else O[k] = mk(fmaf(ct[k], dr, -st[k] * di),
                           fmaf(ct[k], di,  st[k] * dr));
        }

        // U[2m] = IDFT7(p), U[2m+1] = IDFT7(q) — store straight to smem
        float2* base = &Fs[0][k2][c];
        const int rowF2 = HALF_W * CT_TILE;          // float2 stride per n
        cdft7_store<1>(E, base,          2 * rowF2); // even n = 2m
        cdft7_store<1>(O, base + rowF2,  2 * rowF2); // odd  n = 2m+1
    }
    __syncthreads();

    // ---------------- Stage C: c2r-14 over k2 ----------------
    {
        const float c7[7] = C7_TAB;
        const float s7[7] = S7_TAB;
        const float ct[7] = CT14_TAB;
        const float st[7] = ST14_TAB;
        for (int t = tid; t < 14 * CT_TILE; t += NTHREADS) {
            const int c  = t & (CT_TILE - 1);
            const int n1 = t / CT_TILE;
            float2 V[HALF_W];
#pragma unroll
            for (int k = 0; k < HALF_W; k++) V[k] = Fs[n1][k][c];

            const float a0s = (V[0].x + V[7].x) * (1.0f / 196.0f);
            const float b0s = (V[0].x - V[7].x) * (1.0f / 196.0f);
            float2 a[4], bb[4];
#pragma unroll
            for (int k = 1; k <= 3; k++) {
                a[k] = mk(V[k].x + V[7 - k].x, V[k].y - V[7 - k].y);
                const float dr = V[k].x - V[7 - k].x;
                const float di = V[k].y + V[7 - k].y;
                bb[k] = mk(fmaf(ct[k], dr, -st[k] * di),
                           fmaf(ct[k], di,  st[k] * dr));
            }

            float* orow = out + ((size_t)(b * 196 + n1 * 14)) * NCH + c0 + c;
#pragma unroll
            for (int m = 0; m < 7; m++) {
                float evn = a0s, odd = b0s;
#pragma unroll
                for (int k = 1; k <= 3; k++) {
                    const int j = (k * m) % 7;
                    evn = fmaf(a[k].x,   c7[j] * (2.0f / 196.0f), evn);
                    evn = fmaf(a[k].y,  -s7[j] * (2.0f / 196.0f), evn);
                    odd = fmaf(bb[k].x,  c7[j] * (2.0f / 196.0f), odd);
                    odd = fmaf(bb[k].y, -s7[j] * (2.0f / 196.0f), odd);
                }
                orow[(2 * m)     * NCH] = evn;
                orow[(2 * m + 1) * NCH] = odd;
            }
        }
    }
}

extern "C" void kernel_launch(void* const* d_in, const int* in_sizes, int n_in,
                              void* d_out, int out_size)
{
    const float* x  = (const float*)d_in[0];
    const float* cw = (const float*)d_in[1];
    float* out = (float*)d_out;
    (void)in_sizes; (void)n_in; (void)out_size;

    dim3 grid(NBATCH, NCH / CT_TILE);
    gf_kernel<<<grid, NTHREADS>>>(x, cw, out);
}

// round 5
// speedup vs baseline: 1.5106x; 1.0009x over previous
#include <cuda_runtime.h>

// GlobalFilter: out = irfft2( rfft2(x, ortho) * W, ortho ) per (batch, channel)
// x: [512, 196, 384] f32 ; W: [14, 8, 384, 2] f32 ; out: [512, 196, 384] f32
//
// Round 4: Stages A/C vectorized to float2 (each task owns a channel PAIR,
// halving LDG/STG + L1 wavefronts); smem channel dim padded to 17 to break
// STS bank collisions. Stage B (fwd DIT + fused weight mul + inv DIF,
// in-place E/O pairs) unchanged from round 3.

#define NBATCH 512
#define HALF_W 8
#define NCH    384
#define CT_TILE 16
#define CTP     (CT_TILE + 1)   // padded smem channel dim
#define NTHREADS 128

#define C7_TAB {1.0f, 0.6234898018587336f, -0.2225209339563144f, -0.9009688679024191f, \
                -0.9009688679024191f, -0.2225209339563144f, 0.6234898018587336f}
#define S7_TAB {0.0f, 0.7818314824680298f, 0.9749279121818236f, 0.4338837391175581f, \
                -0.4338837391175581f, -0.9749279121818236f, -0.7818314824680298f}
#define CT14_TAB {1.0f, 0.9009688679024191f, 0.6234898018587336f, 0.2225209339563144f, \
                  -0.2225209339563144f, -0.6234898018587336f, -0.9009688679024191f}
#define ST14_TAB {0.0f, 0.4338837391175581f, 0.7818314824680298f, 0.9749279121818236f, \
                  0.9749279121818236f, 0.7818314824680298f, 0.4338837391175581f}

__device__ __forceinline__ float2 mk(float a, float b) { return make_float2(a, b); }

// Symmetric complex DFT-7 into registers. SGN=-1: e^{-2pi i kn/7}; +1: e^{+}.
template<int SGN>
__device__ __forceinline__ void cdft7(const float2 v[7], float2 X[7]) {
    const float c7[7] = C7_TAB;
    const float s7[7] = S7_TAB;
    float2 tp[4], tm[4];
#pragma unroll
    for (int n = 1; n <= 3; n++) {
        tp[n] = mk(v[n].x + v[7 - n].x, v[n].y + v[7 - n].y);
        tm[n] = mk(v[n].x - v[7 - n].x, v[n].y - v[7 - n].y);
    }
    X[0] = mk(v[0].x + tp[1].x + tp[2].x + tp[3].x,
              v[0].y + tp[1].y + tp[2].y + tp[3].y);
#pragma unroll
    for (int k = 1; k <= 3; k++) {
        float Ar = v[0].x, Ai = v[0].y, Br = 0.0f, Bi = 0.0f;
#pragma unroll
        for (int n = 1; n <= 3; n++) {
            const int j = (k * n) % 7;
            Ar = fmaf(tp[n].x, c7[j], Ar);
            Ai = fmaf(tp[n].y, c7[j], Ai);
            Br = fmaf(tm[n].x, s7[j], Br);
            Bi = fmaf(tm[n].y, s7[j], Bi);
        }
        if (SGN < 0) { X[k] = mk(Ar + Bi, Ai - Br); X[7 - k] = mk(Ar - Bi, Ai + Br); }
        else         { X[k] = mk(Ar - Bi, Ai + Br); X[7 - k] = mk(Ar + Bi, Ai - Br); }
    }
}

// Same DFT-7 but stores results straight to (strided) shared memory.
template<int SGN>
__device__ __forceinline__ void cdft7_store(const float2 v[7], float2* base, const int strideF2) {
    const float c7[7] = C7_TAB;
    const float s7[7] = S7_TAB;
    float2 tp[4], tm[4];
#pragma unroll
    for (int n = 1; n <= 3; n++) {
        tp[n] = mk(v[n].x + v[7 - n].x, v[n].y + v[7 - n].y);
        tm[n] = mk(v[n].x - v[7 - n].x, v[n].y - v[7 - n].y);
    }
    base[0] = mk(v[0].x + tp[1].x + tp[2].x + tp[3].x,
                 v[0].y + tp[1].y + tp[2].y + tp[3].y);
#pragma unroll
    for (int k = 1; k <= 3; k++) {
        float Ar = v[0].x, Ai = v[0].y, Br = 0.0f, Bi = 0.0f;
#pragma unroll
        for (int n = 1; n <= 3; n++) {
            const int j = (k * n) % 7;
            Ar = fmaf(tp[n].x, c7[j], Ar);
            Ai = fmaf(tp[n].y, c7[j], Ai);
            Br = fmaf(tm[n].x, s7[j], Br);
            Bi = fmaf(tm[n].y, s7[j], Bi);
        }
        if (SGN < 0) {
            base[k * strideF2]       = mk(Ar + Bi, Ai - Br);
            base[(7 - k) * strideF2] = mk(Ar - Bi, Ai + Br);
        } else {
            base[k * strideF2]       = mk(Ar - Bi, Ai + Br);
            base[(7 - k) * strideF2] = mk(Ar + Bi, Ai - Br);
        }
    }
}

// Real forward DFT-7: bins 0..3 (bin 0 purely real).
__device__ __forceinline__ void rdft7(const float r[7], float& R0, float2 R[4]) {
    const float c7[7] = C7_TAB;
    const float s7[7] = S7_TAB;
    float tp[4], tm[4];
#pragma unroll
    for (int n = 1; n <= 3; n++) { tp[n] = r[n] + r[7 - n]; tm[n] = r[n] - r[7 - n]; }
    R0 = r[0] + tp[1] + tp[2] + tp[3];
#pragma unroll
    for (int k = 1; k <= 3; k++) {
        float re = r[0], im = 0.0f;
#pragma unroll
        for (int n = 1; n <= 3; n++) {
            const int j = (k * n) % 7;
            re = fmaf(tp[n],  c7[j], re);
            im = fmaf(tm[n], -s7[j], im);
        }
        R[k] = mk(re, im);
    }
}

__global__ __launch_bounds__(NTHREADS, 8)
void gf_kernel(const float* __restrict__ x,
               const float* __restrict__ cw,
               float* __restrict__ out)
{
    __shared__ float2 Fs[14][HALF_W][CTP];   // ~15.2 KB

    const int b   = blockIdx.x;
    const int c0  = blockIdx.y * CT_TILE;
    const int tid = threadIdx.x;

    // ------- Stage A: row rfft-14 over n2, float2 channel pairs -------
    if (tid < 14 * (CT_TILE / 2)) {
        const float ct[7] = CT14_TAB;
        const float st[7] = ST14_TAB;
        const int cp = tid & (CT_TILE / 2 - 1);   // channel pair 0..7
        const int n1 = tid / (CT_TILE / 2);
        const float2* xrow =
            reinterpret_cast<const float2*>(x + ((size_t)(b * 196 + n1 * 14)) * NCH + c0) + cp;
        float2 in2[14];
#pragma unroll
        for (int n = 0; n < 14; n++) in2[n] = xrow[n * (NCH / 2)];

#pragma unroll
        for (int h = 0; h < 2; h++) {
            float ev[7], od[7];
#pragma unroll
            for (int n = 0; n < 7; n++) {
                ev[n] = h ? in2[2 * n].y     : in2[2 * n].x;
                od[n] = h ? in2[2 * n + 1].y : in2[2 * n + 1].x;
            }
            float E0, O0;
            float2 E[4], O[4];
            rdft7(ev, E0, E);
            rdft7(od, O0, O);

            const int c = 2 * cp + h;
            Fs[n1][0][c] = mk(E0 + O0, 0.0f);
            Fs[n1][7][c] = mk(E0 - O0, 0.0f);
#pragma unroll
            for (int k = 1; k <= 3; k++) {  // F[k] = E[k] + (c - i s) O[k]
                const float tr = fmaf(ct[k], O[k].x,  st[k] * O[k].y);
                const float ti = fmaf(ct[k], O[k].y, -st[k] * O[k].x);
                Fs[n1][k][c] = mk(E[k].x + tr, E[k].y + ti);
            }
#pragma unroll
            for (int k = 4; k <= 6; k++) {  // conj-symmetry of E,O
                const float orr = O[7 - k].x, oi = O[7 - k].y;
                const float tr =  fmaf(ct[k], orr, -st[k] * oi);
                const float ti = -fmaf(ct[k], oi,   st[k] * orr);
                Fs[n1][k][c] = mk(E[7 - k].x + tr, -E[7 - k].y + ti);
            }
        }
    }
    __syncthreads();

    // ---- Stage B: fwd DIT-14 + weight mul + inv DIF-14, in-place pairs ----
    {
        const float ct[7] = CT14_TAB;
        const float st[7] = ST14_TAB;
        const int c  = tid & (CT_TILE - 1);
        const int k2 = tid / CT_TILE;   // 0..7

        float2 E[7], O[7];
        {
            float2 ve[7];
#pragma unroll
            for (int n = 0; n < 7; n++) ve[n] = Fs[2 * n][k2][c];
            cdft7<-1>(ve, E);
#pragma unroll
            for (int n = 0; n < 7; n++) ve[n] = Fs[2 * n + 1][k2][c];
            cdft7<-1>(ve, O);
        }

        const float2* W = (const float2*)cw + ((size_t)k2 * NCH + c0 + c);
#pragma unroll
        for (int k = 0; k < 7; k++) {
            float Tr, Ti;
            if (k == 0) { Tr = O[0].x; Ti = O[0].y; }
            else {
                Tr = fmaf(ct[k], O[k].x,  st[k] * O[k].y);
                Ti = fmaf(ct[k], O[k].y, -st[k] * O[k].x);
            }
            const float Gr = E[k].x + Tr, Gi = E[k].y + Ti;   // G[k]
            const float Hr = E[k].x - Tr, Hi = E[k].y - Ti;   // G[k+7]
            const float2 wa = W[(size_t)k * (HALF_W * NCH)];
            const float2 wb = W[(size_t)(k + 7) * (HALF_W * NCH)];
            const float gr = fmaf(Gr, wa.x, -Gi * wa.y);
            const float gi = fmaf(Gr, wa.y,  Gi * wa.x);
            const float hr = fmaf(Hr, wb.x, -Hi * wb.y);
            const float hi = fmaf(Hr, wb.y,  Hi * wb.x);
            // DIF fold: p = g+h (even outputs), q = (g-h) e^{+2pi i k/14} (odd)
            E[k] = mk(gr + hr, gi + hi);
            const float dr = gr - hr, di = gi - hi;
            if (k == 0) O[0] = mk(dr, di);
            else O[k] = mk(fmaf(ct[k], dr, -st[k] * di),
                           fmaf(ct[k], di,  st[k] * dr));
        }

        float2* base = &Fs[0][k2][c];
        const int rowF2 = HALF_W * CTP;              // float2 stride per n
        cdft7_store<1>(E, base,          2 * rowF2); // even n = 2m
        cdft7_store<1>(O, base + rowF2,  2 * rowF2); // odd  n = 2m+1
    }
    __syncthreads();

    // ------- Stage C: c2r-14 over k2, float2 channel pairs -------
    if (tid < 14 * (CT_TILE / 2)) {
        const float c7[7] = C7_TAB;
        const float s7[7] = S7_TAB;
        const float ct[7] = CT14_TAB;
        const float st[7] = ST14_TAB;
        const int cp = tid & (CT_TILE / 2 - 1);
        const int n1 = tid / (CT_TILE / 2);

        float2 o[14];
#pragma unroll
        for (int h = 0; h < 2; h++) {
            const int c = 2 * cp + h;
            float2 V[HALF_W];
#pragma unroll
            for (int k = 0; k < HALF_W; k++) V[k] = Fs[n1][k][c];

            const float a0s = (V[0].x + V[7].x) * (1.0f / 196.0f);
            const float b0s = (V[0].x - V[7].x) * (1.0f / 196.0f);
            float2 a[4], bb[4];
#pragma unroll
            for (int k = 1; k <= 3; k++) {
                a[k] = mk(V[k].x + V[7 - k].x, V[k].y - V[7 - k].y);
                const float dr = V[k].x - V[7 - k].x;
                const float di = V[k].y + V[7 - k].y;
                bb[k] = mk(fmaf(ct[k], dr, -st[k] * di),
                           fmaf(ct[k], di,  st[k] * dr));
            }

#pragma unroll
            for (int m = 0; m < 7; m++) {
                float evn = a0s, odd = b0s;
#pragma unroll
                for (int k = 1; k <= 3; k++) {
                    const int j = (k * m) % 7;
                    evn = fmaf(a[k].x,   c7[j] * (2.0f / 196.0f), evn);
                    evn = fmaf(a[k].y,  -s7[j] * (2.0f / 196.0f), evn);
                    odd = fmaf(bb[k].x,  c7[j] * (2.0f / 196.0f), odd);
                    odd = fmaf(bb[k].y, -s7[j] * (2.0f / 196.0f), odd);
                }
                if (h) { o[2 * m].y = evn; o[2 * m + 1].y = odd; }
                else   { o[2 * m].x = evn; o[2 * m + 1].x = odd; }
            }
        }

        float2* orow =
            reinterpret_cast<float2*>(out + ((size_t)(b * 196 + n1 * 14)) * NCH + c0) + cp;
#pragma unroll
        for (int n = 0; n < 14; n++) orow[n * (NCH / 2)] = o[n];
    }
}

extern "C" void kernel_launch(void* const* d_in, const int* in_sizes, int n_in,
                              void* d_out, int out_size)
{
    const float* x  = (const float*)d_in[0];
    const float* cw = (const float*)d_in[1];
    float* out = (float*)d_out;
    (void)in_sizes; (void)n_in; (void)out_size;

    dim3 grid(NBATCH, NCH / CT_TILE);
    gf_kernel<<<grid, NTHREADS>>>(x, cw, out);
}